// round 1
// baseline (speedup 1.0000x reference)
#include <cuda_runtime.h>

#define NN 50000
#define EE 400000
#define HC 128
#define EPS_SKIP_F 1.000001f

// ---------------- scratch (static device allocations) ----------------
__device__ float g_xm[2][NN * HC];      // per-branch transformed features
__device__ float g_ssrc[2][NN * 4];     // per-node per-head src logit part
__device__ float g_sdst[2][NN * 4];     // per-node per-head dst logit part
__device__ float g_denom[2][NN * 4];    // softmax denominators
__device__ float g_ebuf[2][EE * 4];     // exp(alpha) per edge per head

// ---------------- kernels ----------------

__global__ void zero_denom_kernel() {
    int i = blockIdx.x * blockDim.x + threadIdx.x;
    if (i < 2 * NN * 4) ((float*)g_denom)[i] = 0.0f;
}

// Fused triple GEMM: y = x @ W for W in {W_low, W_up, W_skip}.
// blockIdx.y selects which. BM=128, BN=128(full), BK=32.
__global__ __launch_bounds__(256, 2) void gemm_kernel(
    const float* __restrict__ x,
    const float* __restrict__ Wl,
    const float* __restrict__ Wu,
    const float* __restrict__ Ws,
    float* __restrict__ out_skip)
{
    __shared__ float As[32][129];   // transposed x tile: As[k][m], pad for conflict-free
    __shared__ float Bs[32][128];   // W tile: Bs[k][n]

    const int by = blockIdx.y;
    const float* __restrict__ W = (by == 0) ? Wl : ((by == 1) ? Wu : Ws);
    float* __restrict__ out = (by == 0) ? g_xm[0] : ((by == 1) ? g_xm[1] : out_skip);

    const int bm0 = blockIdx.x * 128;
    const int t = threadIdx.x;
    const int tx = t & 15;
    const int ty = t >> 4;

    float acc[8][8];
#pragma unroll
    for (int i = 0; i < 8; i++)
#pragma unroll
        for (int j = 0; j < 8; j++) acc[i][j] = 0.0f;

    for (int k0 = 0; k0 < 128; k0 += 32) {
        // load x tile (128 rows x 32 cols), store transposed
        {
            const int col4 = t & 7;    // k-offset/4
            const int rowb = t >> 3;   // 0..31
#pragma unroll
            for (int i = 0; i < 4; i++) {
                const int row = rowb + 32 * i;
                const int m = bm0 + row;
                float4 v = make_float4(0.f, 0.f, 0.f, 0.f);
                if (m < NN) v = *(const float4*)&x[m * 128 + k0 + col4 * 4];
                As[col4 * 4 + 0][row] = v.x;
                As[col4 * 4 + 1][row] = v.y;
                As[col4 * 4 + 2][row] = v.z;
                As[col4 * 4 + 3][row] = v.w;
            }
        }
        // load W tile (32 rows x 128 cols)
        {
            const int n4 = t & 31;   // n/4
            const int kk = t >> 5;   // 0..7
#pragma unroll
            for (int i = 0; i < 4; i++) {
                const int k = kk + 8 * i;
                float4 v = *(const float4*)&W[(k0 + k) * 128 + n4 * 4];
                *(float4*)&Bs[k][n4 * 4] = v;
            }
        }
        __syncthreads();

#pragma unroll
        for (int k = 0; k < 32; k++) {
            float a[8], b[8];
#pragma unroll
            for (int i = 0; i < 8; i++) a[i] = As[k][ty * 8 + i];
            float4 b0 = *(float4*)&Bs[k][tx * 8];
            float4 b1 = *(float4*)&Bs[k][tx * 8 + 4];
            b[0] = b0.x; b[1] = b0.y; b[2] = b0.z; b[3] = b0.w;
            b[4] = b1.x; b[5] = b1.y; b[6] = b1.z; b[7] = b1.w;
#pragma unroll
            for (int i = 0; i < 8; i++)
#pragma unroll
                for (int j = 0; j < 8; j++) acc[i][j] += a[i] * b[j];
        }
        __syncthreads();
    }

    const float scale = (by == 2) ? EPS_SKIP_F : 1.0f;
#pragma unroll
    for (int i = 0; i < 8; i++) {
        const int m = bm0 + ty * 8 + i;
        if (m < NN) {
#pragma unroll
            for (int j = 0; j < 8; j += 4) {
                float4 v = make_float4(acc[i][j + 0] * scale,
                                       acc[i][j + 1] * scale,
                                       acc[i][j + 2] * scale,
                                       acc[i][j + 3] * scale);
                *(float4*)&out[m * 128 + tx * 8 + j] = v;
            }
        }
    }
}

// Per-node per-head attention logit parts: s = xm[n,h,:] . a[h,:]
__global__ void s_kernel(const float* __restrict__ asl, const float* __restrict__ adl,
                         const float* __restrict__ asu, const float* __restrict__ adu)
{
    int idx = blockIdx.x * blockDim.x + threadIdx.x;
    if (idx >= 2 * NN * 4) return;
    const int branch = idx / (NN * 4);
    const int r = idx - branch * (NN * 4);
    const int n = r >> 2;
    const int h = r & 3;
    const float* __restrict__ xm = g_xm[branch];
    const float* __restrict__ asrc = branch ? asu : asl;
    const float* __restrict__ adst = branch ? adu : adl;
    const float* __restrict__ xr = &xm[n * 128 + h * 32];
    float ss = 0.f, sd = 0.f;
#pragma unroll
    for (int i = 0; i < 32; i++) {
        float v = xr[i];
        ss += v * asrc[h * 32 + i];
        sd += v * adst[h * 32 + i];
    }
    g_ssrc[branch][r] = ss;
    g_sdst[branch][r] = sd;
}

__device__ __forceinline__ float lrelu_exp(float a) {
    a = (a > 0.f) ? a : 0.01f * a;
    return __expf(a);
}

// Pass 1: per edge, compute exp(leaky_relu(logit)) for all 4 heads,
// store it and accumulate softmax denominator at the target node.
__global__ void pass1_kernel(const int* __restrict__ t0, const int* __restrict__ s0,
                             const int* __restrict__ t1, const int* __restrict__ s1)
{
    int idx = blockIdx.x * blockDim.x + threadIdx.x;
    if (idx >= 2 * EE) return;
    const int branch = (idx >= EE) ? 1 : 0;
    const int e = idx - branch * EE;
    const int tgt = (branch ? t1 : t0)[e];
    const int src = (branch ? s1 : s0)[e];
    float4 ss = *(const float4*)&g_ssrc[branch][src * 4];
    float4 sd = *(const float4*)&g_sdst[branch][tgt * 4];
    float ex = lrelu_exp(ss.x + sd.x);
    float ey = lrelu_exp(ss.y + sd.y);
    float ez = lrelu_exp(ss.z + sd.z);
    float ew = lrelu_exp(ss.w + sd.w);
    *(float4*)&g_ebuf[branch][e * 4] = make_float4(ex, ey, ez, ew);
    float* p = &g_denom[branch][tgt * 4];
    asm volatile("red.global.add.v4.f32 [%0], {%1,%2,%3,%4};"
                 :: "l"(p), "f"(ex), "f"(ey), "f"(ez), "f"(ew) : "memory");
}

// Pass 2: one warp per (branch, edge). Lane l handles head l>>3, 4 channels.
// out[tgt] += xm[src] * (e / denom[tgt]) via vector red.
__global__ void pass2_kernel(const int* __restrict__ t0, const int* __restrict__ s0,
                             const int* __restrict__ t1, const int* __restrict__ s1,
                             float* __restrict__ out)
{
    const int gw = (blockIdx.x * blockDim.x + threadIdx.x) >> 5;
    if (gw >= 2 * EE) return;
    const int lane = threadIdx.x & 31;
    const int branch = (gw >= EE) ? 1 : 0;
    const int e = gw - branch * EE;
    const int tgt = (branch ? t1 : t0)[e];
    const int src = (branch ? s1 : s0)[e];
    const int h = lane >> 3;
    const float eh = g_ebuf[branch][e * 4 + h];
    const float dh = g_denom[branch][tgt * 4 + h];
    const float w = eh / (dh + 1e-16f);
    const float4 v = *(const float4*)&g_xm[branch][src * 128 + lane * 4];
    float* p = &out[tgt * 128 + lane * 4];
    asm volatile("red.global.add.v4.f32 [%0], {%1,%2,%3,%4};"
                 :: "l"(p), "f"(v.x * w), "f"(v.y * w), "f"(v.z * w), "f"(v.w * w)
                 : "memory");
}

__global__ void relu_kernel(float* __restrict__ out) {
    int i = blockIdx.x * blockDim.x + threadIdx.x;
    if (i < NN * HC) out[i] = fmaxf(out[i], 0.0f);
}

// ---------------- launch ----------------
extern "C" void kernel_launch(void* const* d_in, const int* in_sizes, int n_in,
                              void* d_out, int out_size)
{
    const float* x      = (const float*)d_in[0];
    const float* W_low  = (const float*)d_in[1];
    const float* a_sl   = (const float*)d_in[2];
    const float* a_dl   = (const float*)d_in[3];
    const float* W_up   = (const float*)d_in[4];
    const float* a_su   = (const float*)d_in[5];
    const float* a_du   = (const float*)d_in[6];
    const float* W_skip = (const float*)d_in[7];
    const int* lower_tgt = (const int*)d_in[8];
    const int* lower_src = (const int*)d_in[9];
    const int* upper_tgt = (const int*)d_in[10];
    const int* upper_src = (const int*)d_in[11];
    float* out = (float*)d_out;

    // 1. zero softmax denominators
    zero_denom_kernel<<<(2 * NN * 4 + 255) / 256, 256>>>();

    // 2. fused triple GEMM (also writes skip*EPS into out)
    dim3 ggrid((NN + 127) / 128, 3);
    gemm_kernel<<<ggrid, 256>>>(x, W_low, W_up, W_skip, out);

    // 3. per-node logit parts
    s_kernel<<<(2 * NN * 4 + 255) / 256, 256>>>(a_sl, a_dl, a_su, a_du);

    // 4. edge softmax numerators + denominators
    pass1_kernel<<<(2 * EE + 255) / 256, 256>>>(lower_tgt, lower_src, upper_tgt, upper_src);

    // 5. weighted aggregation (warp per edge)
    {
        long long threads = (long long)2 * EE * 32;
        int blocks = (int)((threads + 255) / 256);
        pass2_kernel<<<blocks, 256>>>(lower_tgt, lower_src, upper_tgt, upper_src, out);
    }

    // 6. final relu
    relu_kernel<<<(NN * HC + 255) / 256, 256>>>(out);
}